// round 12
// baseline (speedup 1.0000x reference)
#include <cuda_runtime.h>
#include <cuda_fp16.h>
#include <math.h>

#define N_NODES 50000
#define N_EDGES 800000
#define IN_DIM 50
#define HID 64
#define HEADS 4
#define NLAYERS 3
#define NC 12
#define INV_SQRT_C 0.25f
#define LN_EPS 1e-5f
#define SCAN_BLK ((N_NODES + 1023) / 1024)   // 49
#define NTILES ((N_NODES + 63) / 64)         // 782
#define G4_BLOCKS ((NTILES + 1) / 2)         // 391
#define PREPW_BLK ((13 * 4096 + 255) / 256)  // 208
#define HIST_BLK ((N_EDGES + 255) / 256)     // 3125
#define SCAT_BLK ((N_EDGES + 511) / 512)     // 1563
#define LOGIT_BLK ((N_EDGES + 31) / 32)      // 25000 blocks of 256 (8 warps x 4 edges)

typedef unsigned long long ull;

__device__ __forceinline__ ull ff2(ull a, ull b, ull c) {
    ull d;
    asm("fma.rn.f32x2 %0, %1, %2, %3;" : "=l"(d) : "l"(a), "l"(b), "l"(c));
    return d;
}
__device__ __forceinline__ ull packf2(float lo, float hi) {
    return ((ull)__float_as_uint(hi) << 32) | (ull)__float_as_uint(lo);
}
__device__ __forceinline__ float sum2(ull v) {
    return __uint_as_float((unsigned)(v & 0xffffffffu)) + __uint_as_float((unsigned)(v >> 32));
}

// ---------------- scratch ----------------------------------------------------
__device__ __align__(16) float  g_h[N_NODES * HID];
__device__ __align__(16) __half g_hh[N_NODES * HID];
__device__ __align__(16) __half g_qh[N_NODES * HID];   // fp16 q (pre-scaled)
__device__ __align__(16) __half g_kh[N_NODES * HID];   // fp16 k
__device__ __align__(16) __half g_vh[N_NODES * HID];   // fp16 v
__device__ __align__(16) float  g_skip[N_NODES * HID];
__device__ __align__(16) __half g_wt[13 * 64 * 72];
__device__ __align__(16) float  g_ex[N_EDGES * 4];     // exp(logit) per (edge, head)
__device__ int   g_edst[N_EDGES];
__device__ int   g_cnt[N_NODES];
__device__ int   g_rowptr[N_NODES + 1];
__device__ int   g_fill[N_NODES];
__device__ ull   g_edge[N_EDGES];                      // (ea<<32 | src), CSR order
__device__ int   g_psum[64];
__device__ int   g_scan_ctr;

// ================= device bodies =============================================

__device__ __forceinline__ void ingemm_body(int bid, int t,
                         const float* __restrict__ x,
                         const float* __restrict__ Win,
                         const float* __restrict__ b_in,
                         float* xs) {
    int c = t & 63, rg = t >> 6;
    ull w2[26];
    #pragma unroll
    for (int k = 0; k < 25; k++)
        w2[k] = packf2(Win[(2 * k) * HID + c], Win[(2 * k + 1) * HID + c]);
    w2[25] = 0ull;
    int n0 = bid * 64;
    for (int idx = t; idx < 64 * IN_DIM; idx += 256) {
        int r = idx / IN_DIM, k = idx % IN_DIM;
        int row = n0 + r;
        xs[r * 52 + k] = (row < N_NODES) ? x[row * IN_DIM + k] : 0.f;
    }
    if (rg == 0) { xs[c * 52 + 50] = 0.f; xs[c * 52 + 51] = 0.f; }
    __syncthreads();
    float bias = b_in[c];
    int rend = min(rg * 16 + 16, N_NODES - n0);
    for (int r = rg * 16; r < rend; r++) {
        const ulonglong2* hr = (const ulonglong2*)&xs[r * 52];
        ull acc_a = packf2(bias, 0.f), acc_b = 0ull;
        #pragma unroll
        for (int kk = 0; kk < 13; kk++) {
            ulonglong2 hv = hr[kk];
            acc_a = ff2(w2[2 * kk + 0], hv.x, acc_a);
            acc_b = ff2(w2[2 * kk + 1], hv.y, acc_b);
        }
        float acc = sum2(acc_a) + sum2(acc_b);
        g_h[(n0 + r) * HID + c] = acc;
        g_hh[(n0 + r) * HID + c] = __float2half_rn(acc);
    }
}

__device__ __forceinline__ void prepw_body(int id,
                         const float* __restrict__ Wq, const float* __restrict__ Wk,
                         const float* __restrict__ Wv, const float* __restrict__ Wsk,
                         const float* __restrict__ Wc1) {
    if (id >= 13 * 4096) return;
    int k = id & 63, n = (id >> 6) & 63, m = id >> 12;
    const float* W;
    float scal = 1.f;
    if (m == 12) W = Wc1;
    else {
        int li = m >> 2, mat = m & 3;
        if (mat == 0)      { W = Wq + li * 4096; scal = INV_SQRT_C; }
        else if (mat == 1) W = Wk  + li * 4096;
        else if (mat == 2) W = Wv  + li * 4096;
        else               W = Wsk + li * 4096;
    }
    g_wt[(m * 64 + n) * 72 + k] = __float2half_rn(W[k * 64 + n] * scal);
}

__device__ __forceinline__ void gemm4_body(int li, int t, int tile_start, int tile_stride,
                        const float* __restrict__ bq, const float* __restrict__ bk,
                        const float* __restrict__ bv, const float* __restrict__ bsk) {
    __shared__ __half As[64][72];
    __shared__ __half Bs[4][64][72];
    __shared__ float  bias_s[4][64];

    int w = t >> 5, lane = t & 31;
    int mat = w & 3, rg = w >> 2;

    const float* b;
    if (mat == 0)      b = bq  + li * 64;
    else if (mat == 1) b = bk  + li * 64;
    else if (mat == 2) b = bv  + li * 64;
    else               b = bsk + li * 64;
    float scal = (mat == 0) ? INV_SQRT_C : 1.f;

    {
        const uint4* src = (const uint4*)(g_wt + (li * 4 + mat) * 64 * 72);
        uint4* dst = (uint4*)&Bs[mat][0][0];
        for (int idx = rg * 32 + lane; idx < 576; idx += 128)
            dst[idx] = src[idx];
        if (rg == 0)
            for (int c = lane; c < 64; c += 32) bias_s[mat][c] = b[c] * scal;
    }

    int g = lane >> 2, tig = lane & 3;
    int r0 = rg * 16;
    int arow = t >> 3, acol = (t & 7) * 8;

    for (int tile = tile_start; tile < NTILES; tile += tile_stride) {
        int n0 = tile * 64;
        __syncthreads();
        {
            int row = n0 + arow;
            uint4 v = make_uint4(0u, 0u, 0u, 0u);
            if (row < N_NODES) v = *(const uint4*)&g_hh[row * 64 + acol];
            *(uint4*)&As[arow][acol] = v;
        }
        __syncthreads();

        unsigned afr[4][4];
        #pragma unroll
        for (int ks = 0; ks < 4; ks++) {
            int k0 = ks * 16;
            afr[ks][0] = *(const unsigned*)&As[r0 + g][k0 + 2 * tig];
            afr[ks][1] = *(const unsigned*)&As[r0 + g + 8][k0 + 2 * tig];
            afr[ks][2] = *(const unsigned*)&As[r0 + g][k0 + 2 * tig + 8];
            afr[ks][3] = *(const unsigned*)&As[r0 + g + 8][k0 + 2 * tig + 8];
        }

        int row0 = n0 + r0 + g;
        int row1 = row0 + 8;

        #pragma unroll
        for (int nt = 0; nt < 8; nt++) {
            int col = nt * 8 + 2 * tig;
            float c0 = bias_s[mat][col], c1 = bias_s[mat][col + 1];
            float c2 = c0, c3 = c1;
            #pragma unroll
            for (int ks = 0; ks < 4; ks++) {
                unsigned b0 = *(const unsigned*)&Bs[mat][nt * 8 + g][ks * 16 + 2 * tig];
                unsigned b1 = *(const unsigned*)&Bs[mat][nt * 8 + g][ks * 16 + 2 * tig + 8];
                asm volatile(
                    "mma.sync.aligned.m16n8k16.row.col.f32.f16.f16.f32 "
                    "{%0,%1,%2,%3}, {%4,%5,%6,%7}, {%8,%9}, {%0,%1,%2,%3};"
                    : "+f"(c0), "+f"(c1), "+f"(c2), "+f"(c3)
                    : "r"(afr[ks][0]), "r"(afr[ks][1]), "r"(afr[ks][2]), "r"(afr[ks][3]),
                      "r"(b0), "r"(b1));
            }
            if (mat == 3) {
                if (row0 < N_NODES) *(float2*)&g_skip[row0 * 64 + col] = make_float2(c0, c1);
                if (row1 < N_NODES) *(float2*)&g_skip[row1 * 64 + col] = make_float2(c2, c3);
            } else {
                __half* outp = (mat == 0) ? g_qh : (mat == 1) ? g_kh : g_vh;
                if (row0 < N_NODES) *(__half2*)&outp[row0 * 64 + col] = __floats2half2_rn(c0, c1);
                if (row1 < N_NODES) *(__half2*)&outp[row1 * 64 + col] = __floats2half2_rn(c2, c3);
            }
        }
    }
}

__device__ __forceinline__ void scatter_body(int e, const int* __restrict__ ei,
                                             const float* __restrict__ ea) {
    if (e < N_EDGES) {
        int dst = ei[N_EDGES + e];
        int base = g_rowptr[dst] + g_psum[dst >> 10];
        int pos = base + atomicAdd(&g_fill[dst], 1);
        g_edge[pos] = ((ull)__float_as_uint(ea[e]) << 32) | (unsigned)ei[e];
        g_edst[pos] = dst;
    }
}

// ================= kernels ===================================================

__global__ __launch_bounds__(256) void k_fused1(
        const float* __restrict__ x, const float* __restrict__ Win,
        const float* __restrict__ b_in,
        const float* __restrict__ Wq, const float* __restrict__ Wk,
        const float* __restrict__ Wv, const float* __restrict__ Wsk,
        const float* __restrict__ Wc1,
        const int* __restrict__ ei) {
    __shared__ __align__(16) float xs[64 * 52];
    int b = blockIdx.x, t = threadIdx.x;
    if (b < NTILES) {
        ingemm_body(b, t, x, Win, b_in, xs);
    } else if (b < NTILES + PREPW_BLK) {
        prepw_body((b - NTILES) * 256 + t, Wq, Wk, Wv, Wsk, Wc1);
    } else {
        int e = (b - NTILES - PREPW_BLK) * 256 + t;
        if (e < N_NODES) g_fill[e] = 0;
        if (e < N_EDGES) atomicAdd(&g_cnt[ei[N_EDGES + e]], 1);
    }
}

__global__ void k_scan() {
    __shared__ int wsum[32];
    __shared__ int s_last;
    __shared__ int w0tot;
    int t = threadIdx.x, lane = t & 31, wid = t >> 5;
    int i = blockIdx.x * 1024 + t;
    int v = (i < N_NODES) ? g_cnt[i] : 0;
    if (i < N_NODES) g_cnt[i] = 0;
    int incl = v;
    #pragma unroll
    for (int o = 1; o < 32; o <<= 1) {
        int u = __shfl_up_sync(0xffffffffu, incl, o);
        if (lane >= o) incl += u;
    }
    if (lane == 31) wsum[wid] = incl;
    __syncthreads();
    if (wid == 0) {
        int ws = wsum[lane];
        int wincl = ws;
        #pragma unroll
        for (int o = 1; o < 32; o <<= 1) {
            int u = __shfl_up_sync(0xffffffffu, wincl, o);
            if (lane >= o) wincl += u;
        }
        wsum[lane] = wincl - ws;
        if (lane == 31) g_psum[blockIdx.x] = wincl;
    }
    __syncthreads();
    int excl = incl - v + wsum[wid];
    if (i < N_NODES) g_rowptr[i] = excl;

    __threadfence();
    if (t == 0) s_last = (atomicAdd(&g_scan_ctr, 1) == SCAN_BLK - 1) ? 1 : 0;
    __syncthreads();
    if (s_last) {
        int v2 = (t < SCAN_BLK) ? *((volatile int*)g_psum + t) : 0;
        int incl2 = v2;
        if (t < 64) {
            #pragma unroll
            for (int o = 1; o < 32; o <<= 1) {
                int u = __shfl_up_sync(0xffffffffu, incl2, o);
                if (lane >= o) incl2 += u;
            }
            if (t == 31) w0tot = incl2;
        }
        __syncthreads();
        if (t < 64) {
            int excl2 = incl2 - v2 + ((t >= 32) ? w0tot : 0);
            if (t < SCAN_BLK) g_psum[t] = excl2;
            if (t == SCAN_BLK - 1) g_rowptr[N_NODES] = v2;
        }
        if (t == 0) g_scan_ctr = 0;
    }
}

__global__ __launch_bounds__(512) void k_gemm4sc(int li,
                        const float* __restrict__ bq, const float* __restrict__ bk,
                        const float* __restrict__ bv, const float* __restrict__ bsk,
                        const int* __restrict__ ei, const float* __restrict__ ea) {
    if (blockIdx.x < G4_BLOCKS) {
        gemm4_body(li, threadIdx.x, blockIdx.x, G4_BLOCKS, bq, bk, bv, bsk);
    } else {
        int e = (blockIdx.x - G4_BLOCKS) * 512 + threadIdx.x;
        scatter_body(e, ei, ea);
    }
}

__global__ __launch_bounds__(512) void k_gemm4(int li,
                        const float* __restrict__ bq, const float* __restrict__ bk,
                        const float* __restrict__ bv, const float* __restrict__ bsk) {
    gemm4_body(li, threadIdx.x, blockIdx.x, G4_BLOCKS, bq, bk, bv, bsk);
}

// ---------------- pass 1: edge-parallel logits + exp -------------------------
// 8-lane group per edge; lane owns 8 channels; head = 2 lanes (1 shfl)
__global__ __launch_bounds__(256) void k_logits(int li, const float* __restrict__ Wedge) {
    int lane = threadIdx.x & 31;
    int gw = (blockIdx.x * 256 + threadIdx.x) >> 5;
    int l8 = lane & 7;
    int e = gw * 4 + (lane >> 3);
    const float4* Wp = (const float4*)(Wedge + li * 64);
    float4 wa = Wp[l8 * 2], wb = Wp[l8 * 2 + 1];
    bool valid = e < N_EDGES;
    int eidx = valid ? e : 0;
    ull ed = __ldg(&g_edge[eidx]);
    int dst = __ldg(&g_edst[eidx]);
    int src = (int)(ed & 0xffffffffu);
    float w = __uint_as_float((unsigned)(ed >> 32));
    uint4 kr = *(const uint4*)&g_kh[src * 64 + l8 * 8];
    uint4 qr = *(const uint4*)&g_qh[dst * 64 + l8 * 8];
    float2 k0 = __half22float2(*(const __half2*)&kr.x), q0 = __half22float2(*(const __half2*)&qr.x);
    float2 k1 = __half22float2(*(const __half2*)&kr.y), q1 = __half22float2(*(const __half2*)&qr.y);
    float2 k2 = __half22float2(*(const __half2*)&kr.z), q2 = __half22float2(*(const __half2*)&qr.z);
    float2 k3 = __half22float2(*(const __half2*)&kr.w), q3 = __half22float2(*(const __half2*)&qr.w);
    float s  = q0.x * k0.x + q0.y * k0.y + q1.x * k1.x + q1.y * k1.y
             + q2.x * k2.x + q2.y * k2.y + q3.x * k3.x + q3.y * k3.y;
    float qw = q0.x * wa.x + q0.y * wa.y + q1.x * wa.z + q1.y * wa.w
             + q2.x * wb.x + q2.y * wb.y + q3.x * wb.z + q3.y * wb.w;
    s = fmaf(w, qw, s);
    s += __shfl_xor_sync(0xffffffffu, s, 1, 2);   // head logit in both lanes of pair
    float ex = __expf(s);                          // shift-invariant softmax
    if (valid && !(lane & 1)) g_ex[e * 4 + (l8 >> 1)] = ex;
}

// ---------------- pass 2: warp-per-node aggregate + gate + LN ----------------
// lane owns channels {2L,2L+1}; head = L>>3; NO shfls in edge loop
#define AGG_BODY(E, X, V) { \
    float w_ = __uint_as_float((unsigned)((E) >> 32)); \
    float2 vf_ = __half22float2(*(const __half2*)&(V)); \
    d += (X); spw = fmaf((X), w_, spw); \
    accx = fmaf((X), vf_.x, accx); accy = fmaf((X), vf_.y, accy); \
}
#define AGG_LD(i, J) { e##i = __ldg(ep + (J)); x##i = __ldg(exq + (size_t)(J) * 4); \
    v##i = __ldg(vp + ((e##i) & 0xffffffffu) * 32 + lane); }

__global__ void k_nodeagg(int li,
                        const float* __restrict__ Wedge,
                        const float* __restrict__ Wbeta,
                        const float* __restrict__ lng,
                        const float* __restrict__ lnb) {
    int n = blockIdx.x * (blockDim.x >> 5) + (threadIdx.x >> 5);
    if (n >= N_NODES) return;
    int lane = threadIdx.x & 31;
    int h = lane >> 3;

    float2 we2 = ((const float2*)Wedge)[li * 32 + lane];

    int j0 = g_rowptr[n] + g_psum[n >> 10];
    int j1 = g_rowptr[n + 1] + g_psum[(n + 1) >> 10];
    int cnt = j1 - j0;
    const ull* ep = g_edge + j0;
    const float* exq = g_ex + (size_t)j0 * 4 + h;
    const unsigned* vp = (const unsigned*)g_vh;

    float d = 0.f, spw = 0.f, accx = 0.f, accy = 0.f;

    ull e0 = 0, e1 = 0, e2 = 0, e3 = 0;
    float x0 = 0.f, x1 = 0.f, x2 = 0.f, x3 = 0.f;
    unsigned v0 = 0u, v1 = 0u, v2 = 0u, v3 = 0u;
    if (cnt > 0) AGG_LD(0, 0);
    if (cnt > 1) AGG_LD(1, 1);
    if (cnt > 2) AGG_LD(2, 2);
    if (cnt > 3) AGG_LD(3, 3);

    int j = 0;
    for (; j + 8 <= cnt; j += 4) {
        AGG_BODY(e0, x0, v0); AGG_LD(0, j + 4);
        AGG_BODY(e1, x1, v1); AGG_LD(1, j + 5);
        AGG_BODY(e2, x2, v2); AGG_LD(2, j + 6);
        AGG_BODY(e3, x3, v3); AGG_LD(3, j + 7);
    }
    int left = cnt - j;
    if (left > 0) AGG_BODY(e0, x0, v0);
    if (left > 1) AGG_BODY(e1, x1, v1);
    if (left > 2) AGG_BODY(e2, x2, v2);
    if (left > 3) AGG_BODY(e3, x3, v3);
    for (int jj = j + 4; jj < cnt; jj++) {
        ull e = __ldg(ep + jj);
        float x = __ldg(exq + (size_t)jj * 4);
        unsigned v = __ldg(vp + (e & 0xffffffffu) * 32 + lane);
        AGG_BODY(e, x, v);
    }

    float inv = 1.f / (d + 1e-16f);
    float ox = (accx + we2.x * spw) * inv;
    float oy = (accy + we2.y * spw) * inv;

    float2 xr = ((const float2*)g_skip)[n * 32 + lane];
    const float2* Wb = (const float2*)(Wbeta + li * 192);
    float2 w1 = Wb[lane], w2 = Wb[32 + lane], w3 = Wb[64 + lane];
    float contrib = ox * w1.x + oy * w1.y + xr.x * w2.x + xr.y * w2.y
                  + (ox - xr.x) * w3.x + (oy - xr.y) * w3.y;
    #pragma unroll
    for (int o = 16; o >= 1; o >>= 1)
        contrib += __shfl_xor_sync(0xffffffffu, contrib, o);
    float beta = 1.f / (1.f + __expf(-contrib));

    float2 hres = ((const float2*)g_h)[n * 32 + lane];
    float zx = fmaf(beta, xr.x - ox, ox) + hres.x;
    float zy = fmaf(beta, xr.y - oy, oy) + hres.y;

    float s1 = zx + zy;
    float s2 = zx * zx + zy * zy;
    #pragma unroll
    for (int o = 16; o >= 1; o >>= 1) {
        s1 += __shfl_xor_sync(0xffffffffu, s1, o);
        s2 += __shfl_xor_sync(0xffffffffu, s2, o);
    }
    float mu  = s1 * (1.f / 64.f);
    float var = s2 * (1.f / 64.f) - mu * mu;
    float rstd = rsqrtf(var + LN_EPS);
    float2 g = ((const float2*)lng)[li * 32 + lane];
    float2 b = ((const float2*)lnb)[li * 32 + lane];
    float hx = (zx - mu) * rstd * g.x + b.x;
    float hy = (zy - mu) * rstd * g.y + b.y;
    ((float2*)g_h)[n * 32 + lane] = make_float2(hx, hy);
    __half2 hh = __floats2half2_rn(hx, hy);
    ((unsigned*)g_hh)[n * 32 + lane] = *(unsigned*)&hh;
}

// ---------------- head: stage1 HMMA + stage2 FFMA2 ---------------------------
__global__ __launch_bounds__(256) void k_final(const float* __restrict__ bc1,
                        const float* __restrict__ Wc2, const float* __restrict__ bc2,
                        float* __restrict__ out) {
    __shared__ __half As[64][72];
    __shared__ __half Bs[64][72];
    __shared__ __align__(16) float h1s[64 * 64];
    __shared__ float bias1[64];

    int t = threadIdx.x;
    int w = t >> 5, lane = t & 31;
    int n0 = blockIdx.x * 64;

    for (int idx = t; idx < 512; idx += 256) {
        int row = n0 + (idx >> 3), col = (idx & 7) * 8;
        uint4 v = make_uint4(0u, 0u, 0u, 0u);
        if (row < N_NODES) v = *(const uint4*)&g_hh[row * 64 + col];
        *(uint4*)&As[idx >> 3][col] = v;
    }
    {
        const uint4* src = (const uint4*)(g_wt + 12 * 64 * 72);
        uint4* dst = (uint4*)&Bs[0][0];
        for (int idx = t; idx < 576; idx += 256) dst[idx] = src[idx];
    }
    if (t < 64) bias1[t] = bc1[t];
    __syncthreads();

    {
        int rg = w & 3, nh = w >> 2;
        int g = lane >> 2, tig = lane & 3;
        int r0 = rg * 16;
        unsigned afr[4][4];
        #pragma unroll
        for (int ks = 0; ks < 4; ks++) {
            int k0 = ks * 16;
            afr[ks][0] = *(const unsigned*)&As[r0 + g][k0 + 2 * tig];
            afr[ks][1] = *(const unsigned*)&As[r0 + g + 8][k0 + 2 * tig];
            afr[ks][2] = *(const unsigned*)&As[r0 + g][k0 + 2 * tig + 8];
            afr[ks][3] = *(const unsigned*)&As[r0 + g + 8][k0 + 2 * tig + 8];
        }
        #pragma unroll
        for (int q = 0; q < 4; q++) {
            int nt = nh * 4 + q;
            int col = nt * 8 + 2 * tig;
            float c0 = bias1[col], c1 = bias1[col + 1];
            float c2 = c0, c3 = c1;
            #pragma unroll
            for (int ks = 0; ks < 4; ks++) {
                unsigned b0 = *(const unsigned*)&Bs[nt * 8 + g][ks * 16 + 2 * tig];
                unsigned b1 = *(const unsigned*)&Bs[nt * 8 + g][ks * 16 + 2 * tig + 8];
                asm volatile(
                    "mma.sync.aligned.m16n8k16.row.col.f32.f16.f16.f32 "
                    "{%0,%1,%2,%3}, {%4,%5,%6,%7}, {%8,%9}, {%0,%1,%2,%3};"
                    : "+f"(c0), "+f"(c1), "+f"(c2), "+f"(c3)
                    : "r"(afr[ks][0]), "r"(afr[ks][1]), "r"(afr[ks][2]), "r"(afr[ks][3]),
                      "r"(b0), "r"(b1));
            }
            *(float2*)&h1s[(r0 + g) * 64 + col]     = make_float2(fmaxf(c0, 0.f), fmaxf(c1, 0.f));
            *(float2*)&h1s[(r0 + g + 8) * 64 + col] = make_float2(fmaxf(c2, 0.f), fmaxf(c3, 0.f));
        }
    }
    __syncthreads();

    if (t < 240) {
        int c2 = t % 12, rg2 = t / 12;
        ull wr2[32];
        #pragma unroll
        for (int k = 0; k < 32; k++)
            wr2[k] = packf2(Wc2[(2 * k) * NC + c2], Wc2[(2 * k + 1) * NC + c2]);
        float b2 = bc2[c2];
        int rmax = min(64, N_NODES - n0);
        for (int r = rg2; r < rmax; r += 20) {
            const ulonglong2* hr = (const ulonglong2*)&h1s[r * 64];
            ull acc_a = packf2(b2, 0.f), acc_b = 0ull;
            #pragma unroll
            for (int kk = 0; kk < 16; kk++) {
                ulonglong2 hv = hr[kk];
                acc_a = ff2(wr2[2 * kk + 0], hv.x, acc_a);
                acc_b = ff2(wr2[2 * kk + 1], hv.y, acc_b);
            }
            out[(n0 + r) * NC + c2] = sum2(acc_a) + sum2(acc_b);
        }
    }
}

// ---------------- launch -----------------------------------------------------
extern "C" void kernel_launch(void* const* d_in, const int* in_sizes, int n_in,
                              void* d_out, int out_size) {
    const float* x     = (const float*)d_in[0];
    const int*   ei    = (const int*)  d_in[1];
    const float* ea    = (const float*)d_in[2];
    const float* Win   = (const float*)d_in[3];
    const float* b_in  = (const float*)d_in[4];
    const float* Wq    = (const float*)d_in[5];
    const float* bq    = (const float*)d_in[6];
    const float* Wk    = (const float*)d_in[7];
    const float* bk    = (const float*)d_in[8];
    const float* Wv    = (const float*)d_in[9];
    const float* bv    = (const float*)d_in[10];
    const float* Wedge = (const float*)d_in[11];
    const float* Wskip = (const float*)d_in[12];
    const float* bskip = (const float*)d_in[13];
    const float* Wbeta = (const float*)d_in[14];
    const float* ln_g  = (const float*)d_in[15];
    const float* ln_b  = (const float*)d_in[16];
    const float* Wc1   = (const float*)d_in[17];
    const float* bc1   = (const float*)d_in[18];
    const float* Wc2   = (const float*)d_in[19];
    const float* bc2   = (const float*)d_in[20];
    float* out = (float*)d_out;

    int nodeblk = (N_NODES + 7) / 8;
    int logitblk = (N_EDGES / 4 + 7) / 8 / 32 * 32;     // 200000 warps / 8 per block
    logitblk = (N_EDGES / 4) / 8;                        // = 25000 exactly

    // launch #4 (ncu capture slot) = k_logits layer 0
    k_fused1<<<NTILES + PREPW_BLK + HIST_BLK, 256>>>(x, Win, b_in,
                Wq, Wk, Wv, Wskip, Wc1, ei);                                // 1
    k_scan<<<SCAN_BLK, 1024>>>();                                           // 2
    k_gemm4sc<<<G4_BLOCKS + SCAT_BLK, 512>>>(0, bq, bk, bv, bskip, ei, ea); // 3
    k_logits<<<logitblk, 256>>>(0, Wedge);                                  // 4 (profiled)
    k_nodeagg<<<nodeblk, 256>>>(0, Wedge, Wbeta, ln_g, ln_b);               // 5

    for (int li = 1; li < NLAYERS; li++) {
        k_gemm4<<<G4_BLOCKS, 512>>>(li, bq, bk, bv, bskip);
        k_logits<<<logitblk, 256>>>(li, Wedge);
        k_nodeagg<<<nodeblk, 256>>>(li, Wedge, Wbeta, ln_g, ln_b);
    }

    k_final<<<NTILES, 256>>>(bc1, Wc2, bc2, out);
}

// round 13
// speedup vs baseline: 1.1024x; 1.1024x over previous
#include <cuda_runtime.h>
#include <cuda_fp16.h>
#include <math.h>

#define N_NODES 50000
#define N_EDGES 800000
#define IN_DIM 50
#define HID 64
#define HEADS 4
#define NLAYERS 3
#define NC 12
#define INV_SQRT_C 0.25f
#define LN_EPS 1e-5f
#define SCAN_BLK ((N_NODES + 1023) / 1024)   // 49
#define NTILES ((N_NODES + 63) / 64)         // 782
#define G4_BLOCKS ((NTILES + 1) / 2)         // 391
#define PREPW_BLK ((13 * 4096 + 255) / 256)  // 208
#define HIST_BLK ((N_EDGES + 255) / 256)     // 3125
#define SCAT_BLK ((N_EDGES + 511) / 512)     // 1563

typedef unsigned long long ull;

__device__ __forceinline__ ull ff2(ull a, ull b, ull c) {
    ull d;
    asm("fma.rn.f32x2 %0, %1, %2, %3;" : "=l"(d) : "l"(a), "l"(b), "l"(c));
    return d;
}
__device__ __forceinline__ ull packf2(float lo, float hi) {
    return ((ull)__float_as_uint(hi) << 32) | (ull)__float_as_uint(lo);
}
__device__ __forceinline__ float sum2(ull v) {
    return __uint_as_float((unsigned)(v & 0xffffffffu)) + __uint_as_float((unsigned)(v >> 32));
}

// ---------------- scratch ----------------------------------------------------
__device__ __align__(16) float  g_h[N_NODES * HID];
__device__ __align__(16) __half g_hh[N_NODES * HID];
__device__ __align__(16) float  g_q[N_NODES * HID];
__device__ __align__(16) float  g_skip[N_NODES * HID];
// kv chunks: per node 16 chunks of 8 halves: chunk c = {k[4c..4c+3], v[4c..4c+3]}
__device__ __align__(16) __half g_kv[N_NODES * 128];
__device__ __align__(16) __half g_wt[13 * 64 * 72];
__device__ int   g_cnt[N_NODES];
__device__ int   g_rowptr[N_NODES + 1];
__device__ int   g_fill[N_NODES];
__device__ ull   g_edge[N_EDGES];                      // (ea<<32 | src)
__device__ int   g_psum[64];
__device__ int   g_scan_ctr;

// ================= device bodies =============================================

__device__ __forceinline__ void ingemm_body(int bid, int t,
                         const float* __restrict__ x,
                         const float* __restrict__ Win,
                         const float* __restrict__ b_in,
                         float* xs) {
    int c = t & 63, rg = t >> 6;
    ull w2[26];
    #pragma unroll
    for (int k = 0; k < 25; k++)
        w2[k] = packf2(Win[(2 * k) * HID + c], Win[(2 * k + 1) * HID + c]);
    w2[25] = 0ull;
    int n0 = bid * 64;
    for (int idx = t; idx < 64 * IN_DIM; idx += 256) {
        int r = idx / IN_DIM, k = idx % IN_DIM;
        int row = n0 + r;
        xs[r * 52 + k] = (row < N_NODES) ? x[row * IN_DIM + k] : 0.f;
    }
    if (rg == 0) { xs[c * 52 + 50] = 0.f; xs[c * 52 + 51] = 0.f; }
    __syncthreads();
    float bias = b_in[c];
    int rend = min(rg * 16 + 16, N_NODES - n0);
    for (int r = rg * 16; r < rend; r++) {
        const ulonglong2* hr = (const ulonglong2*)&xs[r * 52];
        ull acc_a = packf2(bias, 0.f), acc_b = 0ull;
        #pragma unroll
        for (int kk = 0; kk < 13; kk++) {
            ulonglong2 hv = hr[kk];
            acc_a = ff2(w2[2 * kk + 0], hv.x, acc_a);
            acc_b = ff2(w2[2 * kk + 1], hv.y, acc_b);
        }
        float acc = sum2(acc_a) + sum2(acc_b);
        g_h[(n0 + r) * HID + c] = acc;
        g_hh[(n0 + r) * HID + c] = __float2half_rn(acc);
    }
}

__device__ __forceinline__ void prepw_body(int id,
                         const float* __restrict__ Wq, const float* __restrict__ Wk,
                         const float* __restrict__ Wv, const float* __restrict__ Wsk,
                         const float* __restrict__ Wc1) {
    if (id >= 13 * 4096) return;
    int k = id & 63, n = (id >> 6) & 63, m = id >> 12;
    const float* W;
    float scal = 1.f;
    if (m == 12) W = Wc1;
    else {
        int li = m >> 2, mat = m & 3;
        if (mat == 0)      { W = Wq + li * 4096; scal = INV_SQRT_C; }
        else if (mat == 1) W = Wk  + li * 4096;
        else if (mat == 2) W = Wv  + li * 4096;
        else               W = Wsk + li * 4096;
    }
    g_wt[(m * 64 + n) * 72 + k] = __float2half_rn(W[k * 64 + n] * scal);
}

__device__ __forceinline__ void gemm4_body(int li, int t, int tile_start, int tile_stride,
                        const float* __restrict__ bq, const float* __restrict__ bk,
                        const float* __restrict__ bv, const float* __restrict__ bsk) {
    __shared__ __half As[64][72];
    __shared__ __half Bs[4][64][72];
    __shared__ float  bias_s[4][64];

    int w = t >> 5, lane = t & 31;
    int mat = w & 3, rg = w >> 2;

    const float* b;
    if (mat == 0)      b = bq  + li * 64;
    else if (mat == 1) b = bk  + li * 64;
    else if (mat == 2) b = bv  + li * 64;
    else               b = bsk + li * 64;
    float scal = (mat == 0) ? INV_SQRT_C : 1.f;

    {
        const uint4* src = (const uint4*)(g_wt + (li * 4 + mat) * 64 * 72);
        uint4* dst = (uint4*)&Bs[mat][0][0];
        for (int idx = rg * 32 + lane; idx < 576; idx += 128)
            dst[idx] = src[idx];
        if (rg == 0)
            for (int c = lane; c < 64; c += 32) bias_s[mat][c] = b[c] * scal;
    }

    int g = lane >> 2, tig = lane & 3;
    int r0 = rg * 16;
    int arow = t >> 3, acol = (t & 7) * 8;

    for (int tile = tile_start; tile < NTILES; tile += tile_stride) {
        int n0 = tile * 64;
        __syncthreads();
        {
            int row = n0 + arow;
            uint4 v = make_uint4(0u, 0u, 0u, 0u);
            if (row < N_NODES) v = *(const uint4*)&g_hh[row * 64 + acol];
            *(uint4*)&As[arow][acol] = v;
        }
        __syncthreads();

        unsigned afr[4][4];
        #pragma unroll
        for (int ks = 0; ks < 4; ks++) {
            int k0 = ks * 16;
            afr[ks][0] = *(const unsigned*)&As[r0 + g][k0 + 2 * tig];
            afr[ks][1] = *(const unsigned*)&As[r0 + g + 8][k0 + 2 * tig];
            afr[ks][2] = *(const unsigned*)&As[r0 + g][k0 + 2 * tig + 8];
            afr[ks][3] = *(const unsigned*)&As[r0 + g + 8][k0 + 2 * tig + 8];
        }

        int row0 = n0 + r0 + g;
        int row1 = row0 + 8;

        #pragma unroll
        for (int nt = 0; nt < 8; nt++) {
            int col = nt * 8 + 2 * tig;
            float c0 = bias_s[mat][col], c1 = bias_s[mat][col + 1];
            float c2 = c0, c3 = c1;
            #pragma unroll
            for (int ks = 0; ks < 4; ks++) {
                unsigned b0 = *(const unsigned*)&Bs[mat][nt * 8 + g][ks * 16 + 2 * tig];
                unsigned b1 = *(const unsigned*)&Bs[mat][nt * 8 + g][ks * 16 + 2 * tig + 8];
                asm volatile(
                    "mma.sync.aligned.m16n8k16.row.col.f32.f16.f16.f32 "
                    "{%0,%1,%2,%3}, {%4,%5,%6,%7}, {%8,%9}, {%0,%1,%2,%3};"
                    : "+f"(c0), "+f"(c1), "+f"(c2), "+f"(c3)
                    : "r"(afr[ks][0]), "r"(afr[ks][1]), "r"(afr[ks][2]), "r"(afr[ks][3]),
                      "r"(b0), "r"(b1));
            }
            if (mat == 0) {
                if (row0 < N_NODES) *(float2*)&g_q[row0 * 64 + col] = make_float2(c0, c1);
                if (row1 < N_NODES) *(float2*)&g_q[row1 * 64 + col] = make_float2(c2, c3);
            } else if (mat == 3) {
                if (row0 < N_NODES) *(float2*)&g_skip[row0 * 64 + col] = make_float2(c0, c1);
                if (row1 < N_NODES) *(float2*)&g_skip[row1 * 64 + col] = make_float2(c2, c3);
            } else {
                // chunk layout: half index = (col>>2)*8 + (col&3) + (v ? 4 : 0)
                int pos = ((col >> 2) << 3) + (col & 3) + ((mat == 2) ? 4 : 0);
                if (row0 < N_NODES) *(__half2*)&g_kv[row0 * 128 + pos] = __floats2half2_rn(c0, c1);
                if (row1 < N_NODES) *(__half2*)&g_kv[row1 * 128 + pos] = __floats2half2_rn(c2, c3);
            }
        }
    }
}

__device__ __forceinline__ void scatter_body(int e, const int* __restrict__ ei,
                                             const float* __restrict__ ea) {
    if (e < N_EDGES) {
        int dst = ei[N_EDGES + e];
        int base = g_rowptr[dst] + g_psum[dst >> 10];
        int pos = base + atomicAdd(&g_fill[dst], 1);
        g_edge[pos] = ((ull)__float_as_uint(ea[e]) << 32) | (unsigned)ei[e];
    }
}

// ================= kernels ===================================================

__global__ __launch_bounds__(256) void k_fused1(
        const float* __restrict__ x, const float* __restrict__ Win,
        const float* __restrict__ b_in,
        const float* __restrict__ Wq, const float* __restrict__ Wk,
        const float* __restrict__ Wv, const float* __restrict__ Wsk,
        const float* __restrict__ Wc1,
        const int* __restrict__ ei) {
    __shared__ __align__(16) float xs[64 * 52];
    int b = blockIdx.x, t = threadIdx.x;
    if (b < NTILES) {
        ingemm_body(b, t, x, Win, b_in, xs);
    } else if (b < NTILES + PREPW_BLK) {
        prepw_body((b - NTILES) * 256 + t, Wq, Wk, Wv, Wsk, Wc1);
    } else {
        int e = (b - NTILES - PREPW_BLK) * 256 + t;
        if (e < N_NODES) g_fill[e] = 0;
        if (e < N_EDGES) atomicAdd(&g_cnt[ei[N_EDGES + e]], 1);
    }
}

__global__ void k_scan() {
    __shared__ int wsum[32];
    __shared__ int s_last;
    __shared__ int w0tot;
    int t = threadIdx.x, lane = t & 31, wid = t >> 5;
    int i = blockIdx.x * 1024 + t;
    int v = (i < N_NODES) ? g_cnt[i] : 0;
    if (i < N_NODES) g_cnt[i] = 0;
    int incl = v;
    #pragma unroll
    for (int o = 1; o < 32; o <<= 1) {
        int u = __shfl_up_sync(0xffffffffu, incl, o);
        if (lane >= o) incl += u;
    }
    if (lane == 31) wsum[wid] = incl;
    __syncthreads();
    if (wid == 0) {
        int ws = wsum[lane];
        int wincl = ws;
        #pragma unroll
        for (int o = 1; o < 32; o <<= 1) {
            int u = __shfl_up_sync(0xffffffffu, wincl, o);
            if (lane >= o) wincl += u;
        }
        wsum[lane] = wincl - ws;
        if (lane == 31) g_psum[blockIdx.x] = wincl;
    }
    __syncthreads();
    int excl = incl - v + wsum[wid];
    if (i < N_NODES) g_rowptr[i] = excl;

    __threadfence();
    if (t == 0) s_last = (atomicAdd(&g_scan_ctr, 1) == SCAN_BLK - 1) ? 1 : 0;
    __syncthreads();
    if (s_last) {
        int v2 = (t < SCAN_BLK) ? *((volatile int*)g_psum + t) : 0;
        int incl2 = v2;
        if (t < 64) {
            #pragma unroll
            for (int o = 1; o < 32; o <<= 1) {
                int u = __shfl_up_sync(0xffffffffu, incl2, o);
                if (lane >= o) incl2 += u;
            }
            if (t == 31) w0tot = incl2;
        }
        __syncthreads();
        if (t < 64) {
            int excl2 = incl2 - v2 + ((t >= 32) ? w0tot : 0);
            if (t < SCAN_BLK) g_psum[t] = excl2;
            if (t == SCAN_BLK - 1) g_rowptr[N_NODES] = v2;
        }
        if (t == 0) g_scan_ctr = 0;
    }
}

__global__ __launch_bounds__(512) void k_gemm4sc(int li,
                        const float* __restrict__ bq, const float* __restrict__ bk,
                        const float* __restrict__ bv, const float* __restrict__ bsk,
                        const int* __restrict__ ei, const float* __restrict__ ea) {
    if (blockIdx.x < G4_BLOCKS) {
        gemm4_body(li, threadIdx.x, blockIdx.x, G4_BLOCKS, bq, bk, bv, bsk);
    } else {
        int e = (blockIdx.x - G4_BLOCKS) * 512 + threadIdx.x;
        scatter_body(e, ei, ea);
    }
}

__global__ __launch_bounds__(512) void k_gemm4(int li,
                        const float* __restrict__ bq, const float* __restrict__ bk,
                        const float* __restrict__ bv, const float* __restrict__ bsk) {
    gemm4_body(li, threadIdx.x, blockIdx.x, G4_BLOCKS, bq, bk, bv, bsk);
}

// ---------------- fused node kernel v4: warp/node, 2 edges per iteration -----
// lane = (p = lane>>4 edge parity, c = lane&15 channel chunk of 4)
// head of chunk c = c>>2 (4 lanes per head within each half-warp)
#define LDKV4(E) __ldg((const uint4*)g_kv + (((E) & 0xffffffffu) * 16 + c))
#define NB(E, KV, VAL) { \
    float w_ = __uint_as_float((unsigned)((E) >> 32)); \
    float2 ka_ = __half22float2(*(const __half2*)&(KV).x); \
    float2 kb_ = __half22float2(*(const __half2*)&(KV).y); \
    float2 va_ = __half22float2(*(const __half2*)&(KV).z); \
    float2 vb_ = __half22float2(*(const __half2*)&(KV).w); \
    float p_ = q4.x * ka_.x + q4.y * ka_.y + q4.z * kb_.x + q4.w * kb_.y; \
    p_ += __shfl_xor_sync(0xffffffffu, p_, 1, 4); \
    p_ += __shfl_xor_sync(0xffffffffu, p_, 2, 4); \
    float ex_ = __expf(fmaf(w_, qwe, p_)) * (VAL); \
    d += ex_; spw = fmaf(ex_, w_, spw); \
    acc.x = fmaf(ex_, va_.x, acc.x); acc.y = fmaf(ex_, va_.y, acc.y); \
    acc.z = fmaf(ex_, vb_.x, acc.z); acc.w = fmaf(ex_, vb_.y, acc.w); \
}
#define NLD(i, I) { int idx_ = 2 * (I) + p; \
    if (idx_ < cnt) { e##i = __ldg(ep + idx_); val##i = 1.f; } \
    else            { e##i = 0;               val##i = 0.f; } \
    kv##i = LDKV4(e##i); }

__global__ void k_node4(int li,
                        const float* __restrict__ Wedge,
                        const float* __restrict__ Wbeta,
                        const float* __restrict__ lng,
                        const float* __restrict__ lnb) {
    int n = blockIdx.x * (blockDim.x >> 5) + (threadIdx.x >> 5);
    if (n >= N_NODES) return;
    int lane = threadIdx.x & 31;
    int c = lane & 15, p = lane >> 4;

    float4 q4 = ((const float4*)g_q)[n * 16 + c];     // fp32, pre-scaled
    float4 we = ((const float4*)Wedge)[li * 16 + c];

    // per-head dot(q, we): width-4 butterfly (4 lanes per head)
    float pw = q4.x * we.x + q4.y * we.y + q4.z * we.z + q4.w * we.w;
    pw += __shfl_xor_sync(0xffffffffu, pw, 1, 4);
    pw += __shfl_xor_sync(0xffffffffu, pw, 2, 4);
    float qwe = pw;

    int j0 = g_rowptr[n] + g_psum[n >> 10];
    int j1 = g_rowptr[n + 1] + g_psum[(n + 1) >> 10];
    int cnt = j1 - j0;
    const ull* ep = g_edge + j0;
    int mM = (cnt + 1) >> 1;                // iterations (2 edges each)

    float d = 0.f, spw = 0.f;
    float4 acc = make_float4(0.f, 0.f, 0.f, 0.f);

    ull e0 = 0, e1 = 0, e2 = 0, e3 = 0;
    float val0 = 0.f, val1 = 0.f, val2 = 0.f, val3 = 0.f;
    uint4 kv0 = make_uint4(0u,0u,0u,0u), kv1 = kv0, kv2 = kv0, kv3 = kv0;
    NLD(0, 0); NLD(1, 1); NLD(2, 2); NLD(3, 3);

    int i = 0;
    for (; i + 8 <= mM; i += 4) {
        NB(e0, kv0, val0); NLD(0, i + 4);
        NB(e1, kv1, val1); NLD(1, i + 5);
        NB(e2, kv2, val2); NLD(2, i + 6);
        NB(e3, kv3, val3); NLD(3, i + 7);
    }
    NB(e0, kv0, val0);
    NB(e1, kv1, val1);
    NB(e2, kv2, val2);
    NB(e3, kv3, val3);
    for (int ii = i + 4; ii < mM; ii++) {
        NLD(0, ii);
        NB(e0, kv0, val0);
    }

    // merge the two halves (6 xor-16 shuffles)
    d   += __shfl_xor_sync(0xffffffffu, d, 16);
    spw += __shfl_xor_sync(0xffffffffu, spw, 16);
    acc.x += __shfl_xor_sync(0xffffffffu, acc.x, 16);
    acc.y += __shfl_xor_sync(0xffffffffu, acc.y, 16);
    acc.z += __shfl_xor_sync(0xffffffffu, acc.z, 16);
    acc.w += __shfl_xor_sync(0xffffffffu, acc.w, 16);

    float inv = 1.f / (d + 1e-16f);
    float4 o4;
    o4.x = (acc.x + we.x * spw) * inv;
    o4.y = (acc.y + we.y * spw) * inv;
    o4.z = (acc.z + we.z * spw) * inv;
    o4.w = (acc.w + we.w * spw) * inv;

    float4 xr = ((const float4*)g_skip)[n * 16 + c];
    const float4* Wb = (const float4*)(Wbeta + li * 192);
    float4 w1 = Wb[c], w2 = Wb[16 + c], w3 = Wb[32 + c];
    float contrib = o4.x * w1.x + o4.y * w1.y + o4.z * w1.z + o4.w * w1.w
                  + xr.x * w2.x + xr.y * w2.y + xr.z * w2.z + xr.w * w2.w
                  + (o4.x - xr.x) * w3.x + (o4.y - xr.y) * w3.y
                  + (o4.z - xr.z) * w3.z + (o4.w - xr.w) * w3.w;
    #pragma unroll
    for (int o = 8; o >= 1; o >>= 1)
        contrib += __shfl_xor_sync(0xffffffffu, contrib, o, 16);
    float beta = 1.f / (1.f + __expf(-contrib));

    float4 hres = ((const float4*)g_h)[n * 16 + c];
    float4 z;
    z.x = fmaf(beta, xr.x - o4.x, o4.x) + hres.x;
    z.y = fmaf(beta, xr.y - o4.y, o4.y) + hres.y;
    z.z = fmaf(beta, xr.z - o4.z, o4.z) + hres.z;
    z.w = fmaf(beta, xr.w - o4.w, o4.w) + hres.w;

    float s1 = z.x + z.y + z.z + z.w;
    float s2 = z.x * z.x + z.y * z.y + z.z * z.z + z.w * z.w;
    #pragma unroll
    for (int o = 8; o >= 1; o >>= 1) {
        s1 += __shfl_xor_sync(0xffffffffu, s1, o, 16);
        s2 += __shfl_xor_sync(0xffffffffu, s2, o, 16);
    }
    float mu  = s1 * (1.f / 64.f);
    float var = s2 * (1.f / 64.f) - mu * mu;
    float rstd = rsqrtf(var + LN_EPS);
    float4 g = ((const float4*)lng)[li * 16 + c];
    float4 b = ((const float4*)lnb)[li * 16 + c];
    float4 hout;
    hout.x = (z.x - mu) * rstd * g.x + b.x;
    hout.y = (z.y - mu) * rstd * g.y + b.y;
    hout.z = (z.z - mu) * rstd * g.z + b.z;
    hout.w = (z.w - mu) * rstd * g.w + b.w;
    if (p == 0) {
        ((float4*)g_h)[n * 16 + c] = hout;
        __half2 h01 = __floats2half2_rn(hout.x, hout.y);
        __half2 h23 = __floats2half2_rn(hout.z, hout.w);
        uint2 pk; pk.x = *(unsigned*)&h01; pk.y = *(unsigned*)&h23;
        ((uint2*)g_hh)[n * 16 + c] = pk;
    }
}

// ---------------- head: stage1 HMMA + stage2 FFMA2 ---------------------------
__global__ __launch_bounds__(256) void k_final(const float* __restrict__ bc1,
                        const float* __restrict__ Wc2, const float* __restrict__ bc2,
                        float* __restrict__ out) {
    __shared__ __half As[64][72];
    __shared__ __half Bs[64][72];
    __shared__ __align__(16) float h1s[64 * 64];
    __shared__ float bias1[64];

    int t = threadIdx.x;
    int w = t >> 5, lane = t & 31;
    int n0 = blockIdx.x * 64;

    for (int idx = t; idx < 512; idx += 256) {
        int row = n0 + (idx >> 3), col = (idx & 7) * 8;
        uint4 v = make_uint4(0u, 0u, 0u, 0u);
        if (row < N_NODES) v = *(const uint4*)&g_hh[row * 64 + col];
        *(uint4*)&As[idx >> 3][col] = v;
    }
    {
        const uint4* src = (const uint4*)(g_wt + 12 * 64 * 72);
        uint4* dst = (uint4*)&Bs[0][0];
        for (int idx = t; idx < 576; idx += 256) dst[idx] = src[idx];
    }
    if (t < 64) bias1[t] = bc1[t];
    __syncthreads();

    {
        int rg = w & 3, nh = w >> 2;
        int g = lane >> 2, tig = lane & 3;
        int r0 = rg * 16;
        unsigned afr[4][4];
        #pragma unroll
        for (int ks = 0; ks < 4; ks++) {
            int k0 = ks * 16;
            afr[ks][0] = *(const unsigned*)&As[r0 + g][k0 + 2 * tig];
            afr[ks][1] = *(const unsigned*)&As[r0 + g + 8][k0 + 2 * tig];
            afr[ks][2] = *(const unsigned*)&As[r0 + g][k0 + 2 * tig + 8];
            afr[ks][3] = *(const unsigned*)&As[r0 + g + 8][k0 + 2 * tig + 8];
        }
        #pragma unroll
        for (int q = 0; q < 4; q++) {
            int nt = nh * 4 + q;
            int col = nt * 8 + 2 * tig;
            float c0 = bias1[col], c1 = bias1[col + 1];
            float c2 = c0, c3 = c1;
            #pragma unroll
            for (int ks = 0; ks < 4; ks++) {
                unsigned b0 = *(const unsigned*)&Bs[nt * 8 + g][ks * 16 + 2 * tig];
                unsigned b1 = *(const unsigned*)&Bs[nt * 8 + g][ks * 16 + 2 * tig + 8];
                asm volatile(
                    "mma.sync.aligned.m16n8k16.row.col.f32.f16.f16.f32 "
                    "{%0,%1,%2,%3}, {%4,%5,%6,%7}, {%8,%9}, {%0,%1,%2,%3};"
                    : "+f"(c0), "+f"(c1), "+f"(c2), "+f"(c3)
                    : "r"(afr[ks][0]), "r"(afr[ks][1]), "r"(afr[ks][2]), "r"(afr[ks][3]),
                      "r"(b0), "r"(b1));
            }
            *(float2*)&h1s[(r0 + g) * 64 + col]     = make_float2(fmaxf(c0, 0.f), fmaxf(c1, 0.f));
            *(float2*)&h1s[(r0 + g + 8) * 64 + col] = make_float2(fmaxf(c2, 0.f), fmaxf(c3, 0.f));
        }
    }
    __syncthreads();

    if (t < 240) {
        int c2 = t % 12, rg2 = t / 12;
        ull wr2[32];
        #pragma unroll
        for (int k = 0; k < 32; k++)
            wr2[k] = packf2(Wc2[(2 * k) * NC + c2], Wc2[(2 * k + 1) * NC + c2]);
        float b2 = bc2[c2];
        int rmax = min(64, N_NODES - n0);
        for (int r = rg2; r < rmax; r += 20) {
            const ulonglong2* hr = (const ulonglong2*)&h1s[r * 64];
            ull acc_a = packf2(b2, 0.f), acc_b = 0ull;
            #pragma unroll
            for (int kk = 0; kk < 16; kk++) {
                ulonglong2 hv = hr[kk];
                acc_a = ff2(wr2[2 * kk + 0], hv.x, acc_a);
                acc_b = ff2(wr2[2 * kk + 1], hv.y, acc_b);
            }
            out[(n0 + r) * NC + c2] = sum2(acc_a) + sum2(acc_b);
        }
    }
}

// ---------------- launch -----------------------------------------------------
extern "C" void kernel_launch(void* const* d_in, const int* in_sizes, int n_in,
                              void* d_out, int out_size) {
    const float* x     = (const float*)d_in[0];
    const int*   ei    = (const int*)  d_in[1];
    const float* ea    = (const float*)d_in[2];
    const float* Win   = (const float*)d_in[3];
    const float* b_in  = (const float*)d_in[4];
    const float* Wq    = (const float*)d_in[5];
    const float* bq    = (const float*)d_in[6];
    const float* Wk    = (const float*)d_in[7];
    const float* bk    = (const float*)d_in[8];
    const float* Wv    = (const float*)d_in[9];
    const float* bv    = (const float*)d_in[10];
    const float* Wedge = (const float*)d_in[11];
    const float* Wskip = (const float*)d_in[12];
    const float* bskip = (const float*)d_in[13];
    const float* Wbeta = (const float*)d_in[14];
    const float* ln_g  = (const float*)d_in[15];
    const float* ln_b  = (const float*)d_in[16];
    const float* Wc1   = (const float*)d_in[17];
    const float* bc1   = (const float*)d_in[18];
    const float* Wc2   = (const float*)d_in[19];
    const float* bc2   = (const float*)d_in[20];
    float* out = (float*)d_out;

    int nodeblk = (N_NODES + 7) / 8;

    // launch #4 (ncu capture slot) = k_node4 layer 0
    k_fused1<<<NTILES + PREPW_BLK + HIST_BLK, 256>>>(x, Win, b_in,
                Wq, Wk, Wv, Wskip, Wc1, ei);                                // 1
    k_scan<<<SCAN_BLK, 1024>>>();                                           // 2
    k_gemm4sc<<<G4_BLOCKS + SCAT_BLK, 512>>>(0, bq, bk, bv, bskip, ei, ea); // 3
    k_node4<<<nodeblk, 256>>>(0, Wedge, Wbeta, ln_g, ln_b);                 // 4 (profiled)

    for (int li = 1; li < NLAYERS; li++) {
        k_gemm4<<<G4_BLOCKS, 512>>>(li, bq, bk, bv, bskip);
        k_node4<<<nodeblk, 256>>>(li, Wedge, Wbeta, ln_g, ln_b);
    }

    k_final<<<NTILES, 256>>>(bc1, Wc2, bc2, out);
}

// round 14
// speedup vs baseline: 1.7428x; 1.5810x over previous
#include <cuda_runtime.h>
#include <cuda_fp16.h>
#include <math.h>

#define N_NODES 50000
#define N_EDGES 800000
#define IN_DIM 50
#define HID 64
#define HEADS 4
#define NLAYERS 3
#define NC 12
#define INV_SQRT_C 0.25f
#define LN_EPS 1e-5f
#define SCAN_BLK ((N_NODES + 1023) / 1024)   // 49
#define NTILES ((N_NODES + 63) / 64)         // 782
#define G4_BLOCKS ((NTILES + 1) / 2)         // 391
#define PREPW_BLK ((13 * 4096 + 255) / 256)  // 208
#define HIST_BLK ((N_EDGES + 255) / 256)     // 3125
#define SCAT_BLK ((N_EDGES + 511) / 512)     // 1563

typedef unsigned long long ull;

__device__ __forceinline__ ull ff2(ull a, ull b, ull c) {
    ull d;
    asm("fma.rn.f32x2 %0, %1, %2, %3;" : "=l"(d) : "l"(a), "l"(b), "l"(c));
    return d;
}
__device__ __forceinline__ ull packf2(float lo, float hi) {
    return ((ull)__float_as_uint(hi) << 32) | (ull)__float_as_uint(lo);
}
__device__ __forceinline__ float sum2(ull v) {
    return __uint_as_float((unsigned)(v & 0xffffffffu)) + __uint_as_float((unsigned)(v >> 32));
}

// ---------------- scratch ----------------------------------------------------
__device__ __align__(16) float  g_h[N_NODES * HID];
__device__ __align__(16) __half g_hh[N_NODES * HID];
__device__ __align__(16) float  g_q[N_NODES * HID];
__device__ __align__(16) float  g_skip[N_NODES * HID];
// interleaved kv: per node, lane L (0..31) owns halves {k[2L],k[2L+1],v[2L],v[2L+1]}
__device__ __align__(16) __half g_kv[N_NODES * 128];
__device__ __align__(16) __half g_wt[13 * 64 * 72];
__device__ int   g_cnt[N_NODES];
__device__ int   g_rowptr[N_NODES + 1];
__device__ int   g_fill[N_NODES];
__device__ ull   g_edge[N_EDGES];                      // (ea<<32 | src)
__device__ int   g_psum[64];
__device__ int   g_scan_ctr;

// ================= device bodies =============================================

__device__ __forceinline__ void ingemm_body(int bid, int t,
                         const float* __restrict__ x,
                         const float* __restrict__ Win,
                         const float* __restrict__ b_in,
                         float* xs) {
    int c = t & 63, rg = t >> 6;
    ull w2[26];
    #pragma unroll
    for (int k = 0; k < 25; k++)
        w2[k] = packf2(Win[(2 * k) * HID + c], Win[(2 * k + 1) * HID + c]);
    w2[25] = 0ull;
    int n0 = bid * 64;
    for (int idx = t; idx < 64 * IN_DIM; idx += 256) {
        int r = idx / IN_DIM, k = idx % IN_DIM;
        int row = n0 + r;
        xs[r * 52 + k] = (row < N_NODES) ? x[row * IN_DIM + k] : 0.f;
    }
    if (rg == 0) { xs[c * 52 + 50] = 0.f; xs[c * 52 + 51] = 0.f; }
    __syncthreads();
    float bias = b_in[c];
    int rend = min(rg * 16 + 16, N_NODES - n0);
    for (int r = rg * 16; r < rend; r++) {
        const ulonglong2* hr = (const ulonglong2*)&xs[r * 52];
        ull acc_a = packf2(bias, 0.f), acc_b = 0ull;
        #pragma unroll
        for (int kk = 0; kk < 13; kk++) {
            ulonglong2 hv = hr[kk];
            acc_a = ff2(w2[2 * kk + 0], hv.x, acc_a);
            acc_b = ff2(w2[2 * kk + 1], hv.y, acc_b);
        }
        float acc = sum2(acc_a) + sum2(acc_b);
        g_h[(n0 + r) * HID + c] = acc;
        g_hh[(n0 + r) * HID + c] = __float2half_rn(acc);
    }
}

__device__ __forceinline__ void prepw_body(int id,
                         const float* __restrict__ Wq, const float* __restrict__ Wk,
                         const float* __restrict__ Wv, const float* __restrict__ Wsk,
                         const float* __restrict__ Wc1) {
    if (id >= 13 * 4096) return;
    int k = id & 63, n = (id >> 6) & 63, m = id >> 12;
    const float* W;
    float scal = 1.f;
    if (m == 12) W = Wc1;
    else {
        int li = m >> 2, mat = m & 3;
        if (mat == 0)      { W = Wq + li * 4096; scal = INV_SQRT_C; }
        else if (mat == 1) W = Wk  + li * 4096;
        else if (mat == 2) W = Wv  + li * 4096;
        else               W = Wsk + li * 4096;
    }
    g_wt[(m * 64 + n) * 72 + k] = __float2half_rn(W[k * 64 + n] * scal);
}

__device__ __forceinline__ void gemm4_body(int li, int t, int tile_start, int tile_stride,
                        const float* __restrict__ bq, const float* __restrict__ bk,
                        const float* __restrict__ bv, const float* __restrict__ bsk) {
    __shared__ __half As[64][72];
    __shared__ __half Bs[4][64][72];
    __shared__ float  bias_s[4][64];

    int w = t >> 5, lane = t & 31;
    int mat = w & 3, rg = w >> 2;

    const float* b;
    if (mat == 0)      b = bq  + li * 64;
    else if (mat == 1) b = bk  + li * 64;
    else if (mat == 2) b = bv  + li * 64;
    else               b = bsk + li * 64;
    float scal = (mat == 0) ? INV_SQRT_C : 1.f;

    {
        const uint4* src = (const uint4*)(g_wt + (li * 4 + mat) * 64 * 72);
        uint4* dst = (uint4*)&Bs[mat][0][0];
        for (int idx = rg * 32 + lane; idx < 576; idx += 128)
            dst[idx] = src[idx];
        if (rg == 0)
            for (int c = lane; c < 64; c += 32) bias_s[mat][c] = b[c] * scal;
    }

    int g = lane >> 2, tig = lane & 3;
    int r0 = rg * 16;
    int arow = t >> 3, acol = (t & 7) * 8;

    for (int tile = tile_start; tile < NTILES; tile += tile_stride) {
        int n0 = tile * 64;
        __syncthreads();
        {
            int row = n0 + arow;
            uint4 v = make_uint4(0u, 0u, 0u, 0u);
            if (row < N_NODES) v = *(const uint4*)&g_hh[row * 64 + acol];
            *(uint4*)&As[arow][acol] = v;
        }
        __syncthreads();

        unsigned afr[4][4];
        #pragma unroll
        for (int ks = 0; ks < 4; ks++) {
            int k0 = ks * 16;
            afr[ks][0] = *(const unsigned*)&As[r0 + g][k0 + 2 * tig];
            afr[ks][1] = *(const unsigned*)&As[r0 + g + 8][k0 + 2 * tig];
            afr[ks][2] = *(const unsigned*)&As[r0 + g][k0 + 2 * tig + 8];
            afr[ks][3] = *(const unsigned*)&As[r0 + g + 8][k0 + 2 * tig + 8];
        }

        int row0 = n0 + r0 + g;
        int row1 = row0 + 8;

        #pragma unroll
        for (int nt = 0; nt < 8; nt++) {
            int col = nt * 8 + 2 * tig;
            float c0 = bias_s[mat][col], c1 = bias_s[mat][col + 1];
            float c2 = c0, c3 = c1;
            #pragma unroll
            for (int ks = 0; ks < 4; ks++) {
                unsigned b0 = *(const unsigned*)&Bs[mat][nt * 8 + g][ks * 16 + 2 * tig];
                unsigned b1 = *(const unsigned*)&Bs[mat][nt * 8 + g][ks * 16 + 2 * tig + 8];
                asm volatile(
                    "mma.sync.aligned.m16n8k16.row.col.f32.f16.f16.f32 "
                    "{%0,%1,%2,%3}, {%4,%5,%6,%7}, {%8,%9}, {%0,%1,%2,%3};"
                    : "+f"(c0), "+f"(c1), "+f"(c2), "+f"(c3)
                    : "r"(afr[ks][0]), "r"(afr[ks][1]), "r"(afr[ks][2]), "r"(afr[ks][3]),
                      "r"(b0), "r"(b1));
            }
            if (mat == 0) {
                if (row0 < N_NODES) *(float2*)&g_q[row0 * 64 + col] = make_float2(c0, c1);
                if (row1 < N_NODES) *(float2*)&g_q[row1 * 64 + col] = make_float2(c2, c3);
            } else if (mat == 3) {
                if (row0 < N_NODES) *(float2*)&g_skip[row0 * 64 + col] = make_float2(c0, c1);
                if (row1 < N_NODES) *(float2*)&g_skip[row1 * 64 + col] = make_float2(c2, c3);
            } else {
                // interleaved: channels (col,col+1) -> halves (col>>1)*4 + {0,1}(k) / {2,3}(v)
                int pos = ((col >> 1) << 2) + ((mat == 2) ? 2 : 0);
                if (row0 < N_NODES) *(__half2*)&g_kv[row0 * 128 + pos] = __floats2half2_rn(c0, c1);
                if (row1 < N_NODES) *(__half2*)&g_kv[row1 * 128 + pos] = __floats2half2_rn(c2, c3);
            }
        }
    }
}

__device__ __forceinline__ void scatter_body(int e, const int* __restrict__ ei,
                                             const float* __restrict__ ea) {
    if (e < N_EDGES) {
        int dst = ei[N_EDGES + e];
        int base = g_rowptr[dst] + g_psum[dst >> 10];
        int pos = base + atomicAdd(&g_fill[dst], 1);
        g_edge[pos] = ((ull)__float_as_uint(ea[e]) << 32) | (unsigned)ei[e];
    }
}

// ================= kernels ===================================================

__global__ __launch_bounds__(256) void k_fused1(
        const float* __restrict__ x, const float* __restrict__ Win,
        const float* __restrict__ b_in,
        const float* __restrict__ Wq, const float* __restrict__ Wk,
        const float* __restrict__ Wv, const float* __restrict__ Wsk,
        const float* __restrict__ Wc1,
        const int* __restrict__ ei) {
    __shared__ __align__(16) float xs[64 * 52];
    int b = blockIdx.x, t = threadIdx.x;
    if (b < NTILES) {
        ingemm_body(b, t, x, Win, b_in, xs);
    } else if (b < NTILES + PREPW_BLK) {
        prepw_body((b - NTILES) * 256 + t, Wq, Wk, Wv, Wsk, Wc1);
    } else {
        int e = (b - NTILES - PREPW_BLK) * 256 + t;
        if (e < N_NODES) g_fill[e] = 0;
        if (e < N_EDGES) atomicAdd(&g_cnt[ei[N_EDGES + e]], 1);
    }
}

__global__ void k_scan() {
    __shared__ int wsum[32];
    __shared__ int s_last;
    __shared__ int w0tot;
    int t = threadIdx.x, lane = t & 31, wid = t >> 5;
    int i = blockIdx.x * 1024 + t;
    int v = (i < N_NODES) ? g_cnt[i] : 0;
    if (i < N_NODES) g_cnt[i] = 0;
    int incl = v;
    #pragma unroll
    for (int o = 1; o < 32; o <<= 1) {
        int u = __shfl_up_sync(0xffffffffu, incl, o);
        if (lane >= o) incl += u;
    }
    if (lane == 31) wsum[wid] = incl;
    __syncthreads();
    if (wid == 0) {
        int ws = wsum[lane];
        int wincl = ws;
        #pragma unroll
        for (int o = 1; o < 32; o <<= 1) {
            int u = __shfl_up_sync(0xffffffffu, wincl, o);
            if (lane >= o) wincl += u;
        }
        wsum[lane] = wincl - ws;
        if (lane == 31) g_psum[blockIdx.x] = wincl;
    }
    __syncthreads();
    int excl = incl - v + wsum[wid];
    if (i < N_NODES) g_rowptr[i] = excl;

    __threadfence();
    if (t == 0) s_last = (atomicAdd(&g_scan_ctr, 1) == SCAN_BLK - 1) ? 1 : 0;
    __syncthreads();
    if (s_last) {
        int v2 = (t < SCAN_BLK) ? *((volatile int*)g_psum + t) : 0;
        int incl2 = v2;
        if (t < 64) {
            #pragma unroll
            for (int o = 1; o < 32; o <<= 1) {
                int u = __shfl_up_sync(0xffffffffu, incl2, o);
                if (lane >= o) incl2 += u;
            }
            if (t == 31) w0tot = incl2;
        }
        __syncthreads();
        if (t < 64) {
            int excl2 = incl2 - v2 + ((t >= 32) ? w0tot : 0);
            if (t < SCAN_BLK) g_psum[t] = excl2;
            if (t == SCAN_BLK - 1) g_rowptr[N_NODES] = v2;
        }
        if (t == 0) g_scan_ctr = 0;
    }
}

__global__ __launch_bounds__(512) void k_gemm4sc(int li,
                        const float* __restrict__ bq, const float* __restrict__ bk,
                        const float* __restrict__ bv, const float* __restrict__ bsk,
                        const int* __restrict__ ei, const float* __restrict__ ea) {
    if (blockIdx.x < G4_BLOCKS) {
        gemm4_body(li, threadIdx.x, blockIdx.x, G4_BLOCKS, bq, bk, bv, bsk);
    } else {
        int e = (blockIdx.x - G4_BLOCKS) * 512 + threadIdx.x;
        scatter_body(e, ei, ea);
    }
}

__global__ __launch_bounds__(512) void k_gemm4(int li,
                        const float* __restrict__ bq, const float* __restrict__ bk,
                        const float* __restrict__ bv, const float* __restrict__ bsk) {
    gemm4_body(li, threadIdx.x, blockIdx.x, G4_BLOCKS, bq, bk, bv, bsk);
}

// ---------------- fused node kernel (R11 structure): warp/node, 64-thr blocks
#define LDKV(E) __ldg((const uint2*)g_kv + (((E) & 0xffffffffu) * 32 + lane))
#define NODE_BODY(E, R) { \
    float w_ = __uint_as_float((unsigned)((E) >> 32)); \
    float2 kf_ = __half22float2(*(const __half2*)&(R).x); \
    float2 vf_ = __half22float2(*(const __half2*)&(R).y); \
    float p_ = q2.x * kf_.x + q2.y * kf_.y; \
    p_ += __shfl_xor_sync(0xffffffffu, p_, 1, 8); \
    p_ += __shfl_xor_sync(0xffffffffu, p_, 2, 8); \
    p_ += __shfl_xor_sync(0xffffffffu, p_, 4, 8); \
    float ex_ = __expf(fmaf(w_, qwe, p_)); \
    d += ex_; spw = fmaf(ex_, w_, spw); \
    accx = fmaf(ex_, vf_.x, accx); accy = fmaf(ex_, vf_.y, accy); \
}

__global__ __launch_bounds__(64) void k_node3(int li,
                        const float* __restrict__ Wedge,
                        const float* __restrict__ Wbeta,
                        const float* __restrict__ lng,
                        const float* __restrict__ lnb) {
    int n = blockIdx.x * 2 + (threadIdx.x >> 5);
    if (n >= N_NODES) return;
    int lane = threadIdx.x & 31;

    float2 q2  = ((const float2*)g_q)[n * 32 + lane];     // pre-scaled
    float2 we2 = ((const float2*)Wedge)[li * 32 + lane];

    float pw = q2.x * we2.x + q2.y * we2.y;
    pw += __shfl_xor_sync(0xffffffffu, pw, 1, 8);
    pw += __shfl_xor_sync(0xffffffffu, pw, 2, 8);
    pw += __shfl_xor_sync(0xffffffffu, pw, 4, 8);
    float qwe = pw;

    int j0 = g_rowptr[n] + g_psum[n >> 10];
    int j1 = g_rowptr[n + 1] + g_psum[(n + 1) >> 10];
    int cnt = j1 - j0;
    const ull* ep = g_edge + j0;

    float d = 0.f, spw = 0.f, accx = 0.f, accy = 0.f;

    ull e0 = 0, e1 = 0, e2 = 0, e3 = 0;
    uint2 r0 = make_uint2(0u,0u), r1 = r0, r2 = r0, r3 = r0;
    if (cnt > 0) { e0 = __ldg(ep + 0); r0 = LDKV(e0); }
    if (cnt > 1) { e1 = __ldg(ep + 1); r1 = LDKV(e1); }
    if (cnt > 2) { e2 = __ldg(ep + 2); r2 = LDKV(e2); }
    if (cnt > 3) { e3 = __ldg(ep + 3); r3 = LDKV(e3); }

    int j = 0;
    for (; j + 8 <= cnt; j += 4) {
        NODE_BODY(e0, r0); e0 = __ldg(ep + j + 4); r0 = LDKV(e0);
        NODE_BODY(e1, r1); e1 = __ldg(ep + j + 5); r1 = LDKV(e1);
        NODE_BODY(e2, r2); e2 = __ldg(ep + j + 6); r2 = LDKV(e2);
        NODE_BODY(e3, r3); e3 = __ldg(ep + j + 7); r3 = LDKV(e3);
    }
    int left = cnt - j;
    if (left > 0) NODE_BODY(e0, r0);
    if (left > 1) NODE_BODY(e1, r1);
    if (left > 2) NODE_BODY(e2, r2);
    if (left > 3) NODE_BODY(e3, r3);
    for (int jj = j + 4; jj < cnt; jj++) {
        ull e = __ldg(ep + jj); uint2 r = LDKV(e);
        NODE_BODY(e, r);
    }

    float inv = 1.f / (d + 1e-16f);
    float ox = (accx + we2.x * spw) * inv;
    float oy = (accy + we2.y * spw) * inv;

    float2 xr = ((const float2*)g_skip)[n * 32 + lane];
    const float2* Wb = (const float2*)(Wbeta + li * 192);
    float2 w1 = Wb[lane], w2 = Wb[32 + lane], w3 = Wb[64 + lane];
    float contrib = ox * w1.x + oy * w1.y + xr.x * w2.x + xr.y * w2.y
                  + (ox - xr.x) * w3.x + (oy - xr.y) * w3.y;
    #pragma unroll
    for (int o = 16; o >= 1; o >>= 1)
        contrib += __shfl_xor_sync(0xffffffffu, contrib, o);
    float beta = 1.f / (1.f + __expf(-contrib));

    float2 hres = ((const float2*)g_h)[n * 32 + lane];
    float zx = fmaf(beta, xr.x - ox, ox) + hres.x;
    float zy = fmaf(beta, xr.y - oy, oy) + hres.y;

    float s1 = zx + zy;
    float s2 = zx * zx + zy * zy;
    #pragma unroll
    for (int o = 16; o >= 1; o >>= 1) {
        s1 += __shfl_xor_sync(0xffffffffu, s1, o);
        s2 += __shfl_xor_sync(0xffffffffu, s2, o);
    }
    float mu  = s1 * (1.f / 64.f);
    float var = s2 * (1.f / 64.f) - mu * mu;
    float rstd = rsqrtf(var + LN_EPS);
    float2 g = ((const float2*)lng)[li * 32 + lane];
    float2 b = ((const float2*)lnb)[li * 32 + lane];
    float hx = (zx - mu) * rstd * g.x + b.x;
    float hy = (zy - mu) * rstd * g.y + b.y;
    ((float2*)g_h)[n * 32 + lane] = make_float2(hx, hy);
    __half2 hh = __floats2half2_rn(hx, hy);
    ((unsigned*)g_hh)[n * 32 + lane] = *(unsigned*)&hh;
}

// ---------------- head: stage1 HMMA + stage2 FFMA2 ---------------------------
__global__ __launch_bounds__(256) void k_final(const float* __restrict__ bc1,
                        const float* __restrict__ Wc2, const float* __restrict__ bc2,
                        float* __restrict__ out) {
    __shared__ __half As[64][72];
    __shared__ __half Bs[64][72];
    __shared__ __align__(16) float h1s[64 * 64];
    __shared__ float bias1[64];

    int t = threadIdx.x;
    int w = t >> 5, lane = t & 31;
    int n0 = blockIdx.x * 64;

    for (int idx = t; idx < 512; idx += 256) {
        int row = n0 + (idx >> 3), col = (idx & 7) * 8;
        uint4 v = make_uint4(0u, 0u, 0u, 0u);
        if (row < N_NODES) v = *(const uint4*)&g_hh[row * 64 + col];
        *(uint4*)&As[idx >> 3][col] = v;
    }
    {
        const uint4* src = (const uint4*)(g_wt + 12 * 64 * 72);
        uint4* dst = (uint4*)&Bs[0][0];
        for (int idx = t; idx < 576; idx += 256) dst[idx] = src[idx];
    }
    if (t < 64) bias1[t] = bc1[t];
    __syncthreads();

    {
        int rg = w & 3, nh = w >> 2;
        int g = lane >> 2, tig = lane & 3;
        int r0 = rg * 16;
        unsigned afr[4][4];
        #pragma unroll
        for (int ks = 0; ks < 4; ks++) {
            int k0 = ks * 16;
            afr[ks][0] = *(const unsigned*)&As[r0 + g][k0 + 2 * tig];
            afr[ks][1] = *(const unsigned*)&As[r0 + g + 8][k0 + 2 * tig];
            afr[ks][2] = *(const unsigned*)&As[r0 + g][k0 + 2 * tig + 8];
            afr[ks][3] = *(const unsigned*)&As[r0 + g + 8][k0 + 2 * tig + 8];
        }
        #pragma unroll
        for (int q = 0; q < 4; q++) {
            int nt = nh * 4 + q;
            int col = nt * 8 + 2 * tig;
            float c0 = bias1[col], c1 = bias1[col + 1];
            float c2 = c0, c3 = c1;
            #pragma unroll
            for (int ks = 0; ks < 4; ks++) {
                unsigned b0 = *(const unsigned*)&Bs[nt * 8 + g][ks * 16 + 2 * tig];
                unsigned b1 = *(const unsigned*)&Bs[nt * 8 + g][ks * 16 + 2 * tig + 8];
                asm volatile(
                    "mma.sync.aligned.m16n8k16.row.col.f32.f16.f16.f32 "
                    "{%0,%1,%2,%3}, {%4,%5,%6,%7}, {%8,%9}, {%0,%1,%2,%3};"
                    : "+f"(c0), "+f"(c1), "+f"(c2), "+f"(c3)
                    : "r"(afr[ks][0]), "r"(afr[ks][1]), "r"(afr[ks][2]), "r"(afr[ks][3]),
                      "r"(b0), "r"(b1));
            }
            *(float2*)&h1s[(r0 + g) * 64 + col]     = make_float2(fmaxf(c0, 0.f), fmaxf(c1, 0.f));
            *(float2*)&h1s[(r0 + g + 8) * 64 + col] = make_float2(fmaxf(c2, 0.f), fmaxf(c3, 0.f));
        }
    }
    __syncthreads();

    if (t < 240) {
        int c2 = t % 12, rg2 = t / 12;
        ull wr2[32];
        #pragma unroll
        for (int k = 0; k < 32; k++)
            wr2[k] = packf2(Wc2[(2 * k) * NC + c2], Wc2[(2 * k + 1) * NC + c2]);
        float b2 = bc2[c2];
        int rmax = min(64, N_NODES - n0);
        for (int r = rg2; r < rmax; r += 20) {
            const ulonglong2* hr = (const ulonglong2*)&h1s[r * 64];
            ull acc_a = packf2(b2, 0.f), acc_b = 0ull;
            #pragma unroll
            for (int kk = 0; kk < 16; kk++) {
                ulonglong2 hv = hr[kk];
                acc_a = ff2(wr2[2 * kk + 0], hv.x, acc_a);
                acc_b = ff2(wr2[2 * kk + 1], hv.y, acc_b);
            }
            out[(n0 + r) * NC + c2] = sum2(acc_a) + sum2(acc_b);
        }
    }
}

// ---------------- launch -----------------------------------------------------
extern "C" void kernel_launch(void* const* d_in, const int* in_sizes, int n_in,
                              void* d_out, int out_size) {
    const float* x     = (const float*)d_in[0];
    const int*   ei    = (const int*)  d_in[1];
    const float* ea    = (const float*)d_in[2];
    const float* Win   = (const float*)d_in[3];
    const float* b_in  = (const float*)d_in[4];
    const float* Wq    = (const float*)d_in[5];
    const float* bq    = (const float*)d_in[6];
    const float* Wk    = (const float*)d_in[7];
    const float* bk    = (const float*)d_in[8];
    const float* Wv    = (const float*)d_in[9];
    const float* bv    = (const float*)d_in[10];
    const float* Wedge = (const float*)d_in[11];
    const float* Wskip = (const float*)d_in[12];
    const float* bskip = (const float*)d_in[13];
    const float* Wbeta = (const float*)d_in[14];
    const float* ln_g  = (const float*)d_in[15];
    const float* ln_b  = (const float*)d_in[16];
    const float* Wc1   = (const float*)d_in[17];
    const float* bc1   = (const float*)d_in[18];
    const float* Wc2   = (const float*)d_in[19];
    const float* bc2   = (const float*)d_in[20];
    float* out = (float*)d_out;

    int nodeblk = (N_NODES + 1) / 2;     // 2 warps per block

    // launch #4 (ncu capture slot) = k_node3 layer 0
    k_fused1<<<NTILES + PREPW_BLK + HIST_BLK, 256>>>(x, Win, b_in,
                Wq, Wk, Wv, Wskip, Wc1, ei);                                // 1
    k_scan<<<SCAN_BLK, 1024>>>();                                           // 2
    k_gemm4sc<<<G4_BLOCKS + SCAT_BLK, 512>>>(0, bq, bk, bv, bskip, ei, ea); // 3
    k_node3<<<nodeblk, 64>>>(0, Wedge, Wbeta, ln_g, ln_b);                  // 4 (profiled)

    for (int li = 1; li < NLAYERS; li++) {
        k_gemm4<<<G4_BLOCKS, 512>>>(li, bq, bk, bv, bskip);
        k_node3<<<nodeblk, 64>>>(li, Wedge, Wbeta, ln_g, ln_b);
    }

    k_final<<<NTILES, 256>>>(bc1, Wc2, bc2, out);
}